// round 3
// baseline (speedup 1.0000x reference)
#include <cuda_runtime.h>
#include <math.h>

#define NN 50000
#define NE 400000
#define NHID 128
#define INDIM 256
#define NT 4
#define NR 5
#define NH 4
#define DK 32
#define MAXLEN 240
#define NLAYERS 2

// ---------------- scratch (device globals; no allocation) ----------------
__device__ float d_h[(size_t)NN * NHID];
__device__ float d_h2[(size_t)NN * NHID];
__device__ float d_Kn[(size_t)NN * NHID];
__device__ float d_Vn[(size_t)NN * NHID];
__device__ float d_Qn[(size_t)NN * NHID];
__device__ float d_QR[(size_t)NN * NR * NHID];
__device__ float d_VR[(size_t)NN * NR * NHID];
__device__ float d_denom[(size_t)NN * NH];
__device__ float d_aggr[(size_t)NN * NHID];
__device__ float d_gbuf[(size_t)NN * NHID];
__device__ float d_rtetab[MAXLEN * NHID];
__device__ float d_Krte[NT * MAXLEN * NHID];
__device__ float d_Vrte[NT * MAXLEN * NHID];
__device__ float d_VRrte[(size_t)NT * NR * MAXLEN * NHID];
__device__ int d_perm[NN];
__device__ int d_cnt[NT];
__device__ int d_off[NT + 1];
__device__ int d_cur[NT];

__device__ __forceinline__ float gelu_f(float x) {
    return 0.5f * x * (1.0f + erff(x * 0.70710678118654752440f));
}

// ---------------- type bucketing (counting sort by node type) ----------------
__global__ void k_count(const int* __restrict__ nt) {
    int n = blockIdx.x * 256 + threadIdx.x;
    if (n < NN) atomicAdd(&d_cnt[nt[n]], 1);
}
__global__ void k_scan() {
    int s = 0;
    for (int t = 0; t < NT; t++) { d_off[t] = s; d_cur[t] = s; s += d_cnt[t]; }
    d_off[NT] = s;
}
__global__ void k_scatter(const int* __restrict__ nt) {
    int n = blockIdx.x * 256 + threadIdx.x;
    if (n < NN) {
        int p = atomicAdd(&d_cur[nt[n]], 1);
        d_perm[p] = n;
    }
}

// ---------------- type-selected GEMM: C[n,:] = A[n,:] @ W[type[n]] + b ----------------
// 128x128 tile, 256 threads, 8x8 per thread, BK=16.
// EPI: 0 = bias, 1 = bias+GELU, 2 = bias then v*sig(skip[t]) + Hres*(1-sig)
template <int K, int EPI>
__global__ __launch_bounds__(256) void typed_gemm(
    const float* __restrict__ A, const float* __restrict__ W,
    const float* __restrict__ Bias, const float* __restrict__ skipv,
    const float* __restrict__ Hres, float* __restrict__ C)
{
    int b = blockIdx.x;
    int t = -1, row0 = 0, mrows = 0;
#pragma unroll
    for (int tt = 0; tt < NT; tt++) {
        if (t < 0) {
            int c = d_cnt[tt];
            int ntile = (c + 127) >> 7;
            if (b < ntile) {
                t = tt;
                row0 = d_off[tt] + b * 128;
                mrows = c - b * 128;
                if (mrows > 128) mrows = 128;
            } else {
                b -= ntile;
            }
        }
    }
    if (t < 0) return;

    __shared__ float As[16][128];
    __shared__ float Bs[16][128];
    __shared__ int rowidx[128];
    int tid = threadIdx.x;
    if (tid < 128) {
        int m = tid < mrows ? tid : (mrows - 1);
        rowidx[tid] = d_perm[row0 + m];
    }
    __syncthreads();

    const float* Wt = W + (size_t)t * K * NHID;
    float acc[8][8];
#pragma unroll
    for (int j = 0; j < 8; j++)
#pragma unroll
        for (int i = 0; i < 8; i++) acc[j][i] = 0.f;
    int tm = tid >> 4, tn = tid & 15;   // 16x16 threads, each 8x8

    for (int k0 = 0; k0 < K; k0 += 16) {
        // As fill: 128 m x 16 k = 512 float4s; m = s&127 so STS are conflict-free
#pragma unroll
        for (int it = 0; it < 2; it++) {
            int s = tid + it * 256;
            int m = s & 127, kg = (s >> 7) * 4;
            float4 av = *(const float4*)(A + (size_t)rowidx[m] * K + k0 + kg);
            As[kg + 0][m] = av.x; As[kg + 1][m] = av.y;
            As[kg + 2][m] = av.z; As[kg + 3][m] = av.w;
        }
        // Bs fill: 16 k x 128 n
#pragma unroll
        for (int it = 0; it < 2; it++) {
            int s = tid + it * 256;
            int kk = s >> 5, c4 = (s & 31) * 4;
            *(float4*)&Bs[kk][c4] = *(const float4*)(Wt + (size_t)(k0 + kk) * NHID + c4);
        }
        __syncthreads();
#pragma unroll
        for (int kk = 0; kk < 16; kk++) {
            float4 a0 = *(const float4*)&As[kk][tm * 8];
            float4 a1 = *(const float4*)&As[kk][tm * 8 + 4];
            float4 b0 = *(const float4*)&Bs[kk][tn * 8];
            float4 b1 = *(const float4*)&Bs[kk][tn * 8 + 4];
            float av[8] = {a0.x, a0.y, a0.z, a0.w, a1.x, a1.y, a1.z, a1.w};
            float bv[8] = {b0.x, b0.y, b0.z, b0.w, b1.x, b1.y, b1.z, b1.w};
#pragma unroll
            for (int j = 0; j < 8; j++)
#pragma unroll
                for (int i = 0; i < 8; i++)
                    acc[j][i] += av[j] * bv[i];
        }
        __syncthreads();
    }

    float4 bias0 = *(const float4*)(Bias + t * NHID + tn * 8);
    float4 bias1 = *(const float4*)(Bias + t * NHID + tn * 8 + 4);
    float sg = 0.f, om = 0.f;
    if (EPI == 2) {
        float sv = skipv[t];
        sg = 1.f / (1.f + expf(-sv));
        om = 1.f - sg;
    }
#pragma unroll
    for (int j = 0; j < 8; j++) {
        int m = tm * 8 + j;
        if (m < mrows) {
            int gr = rowidx[m];
            float4 v0, v1;
            v0.x = acc[j][0] + bias0.x; v0.y = acc[j][1] + bias0.y;
            v0.z = acc[j][2] + bias0.z; v0.w = acc[j][3] + bias0.w;
            v1.x = acc[j][4] + bias1.x; v1.y = acc[j][5] + bias1.y;
            v1.z = acc[j][6] + bias1.z; v1.w = acc[j][7] + bias1.w;
            if (EPI == 1) {
                v0.x = gelu_f(v0.x); v0.y = gelu_f(v0.y);
                v0.z = gelu_f(v0.z); v0.w = gelu_f(v0.w);
                v1.x = gelu_f(v1.x); v1.y = gelu_f(v1.y);
                v1.z = gelu_f(v1.z); v1.w = gelu_f(v1.w);
            }
            if (EPI == 2) {
                float4 h0 = *(const float4*)(Hres + (size_t)gr * NHID + tn * 8);
                float4 h1 = *(const float4*)(Hres + (size_t)gr * NHID + tn * 8 + 4);
                v0.x = v0.x * sg + h0.x * om; v0.y = v0.y * sg + h0.y * om;
                v0.z = v0.z * sg + h0.z * om; v0.w = v0.w * sg + h0.w * om;
                v1.x = v1.x * sg + h1.x * om; v1.y = v1.y * sg + h1.y * om;
                v1.z = v1.z * sg + h1.z * om; v1.w = v1.w * sg + h1.w * om;
            }
            *(float4*)(C + (size_t)gr * NHID + tn * 8) = v0;
            *(float4*)(C + (size_t)gr * NHID + tn * 8 + 4) = v1;
        }
    }
}

// ---------------- block-diagonal relation transform ----------------
// TRANS (QR): Out[n,r,h*32+d] = s * sum_k M[r,h,d,k] * In[n,h*32+k]
// !TRANS (VR): Out[n,r,h*32+d] =     sum_k In[n,h*32+k] * M[r,h,k,d]
template <bool TRANS>
__global__ __launch_bounds__(640) void qrvr_kernel(
    const float* __restrict__ In, const float* __restrict__ M,
    const float* __restrict__ pri, float scale, float* __restrict__ Out)
{
    int tid = threadIdx.x;
    int r = tid >> 7, rem = tid & 127, h = rem >> 5, d = rem & 31;
    float s = scale;
    if (pri) s *= pri[r * NH + h];
    float ra[DK];
    if (TRANS) {
        const float* base = M + (((size_t)(r * NH + h) * DK + d) * DK);
#pragma unroll
        for (int k = 0; k < DK; k++) ra[k] = base[k] * s;
    } else {
        const float* base = M + ((size_t)(r * NH + h) * DK * DK + d);
#pragma unroll
        for (int k = 0; k < DK; k++) ra[k] = base[k * DK] * s;
    }
    __shared__ float qs[64][NHID];
    int n0 = blockIdx.x * 64;
    for (int i = tid; i < 64 * NHID; i += 640) {
        int ni = i >> 7, c = i & 127;
        int n = n0 + ni;
        qs[ni][c] = (n < NN) ? In[(size_t)n * NHID + c] : 0.f;
    }
    __syncthreads();
    int nmax = NN - n0;
    if (nmax > 64) nmax = 64;
    for (int ni = 0; ni < nmax; ni++) {
        float acc = 0.f;
#pragma unroll
        for (int k4 = 0; k4 < 8; k4++) {
            float4 q4 = *(const float4*)&qs[ni][h * DK + k4 * 4];
            acc += ra[k4 * 4] * q4.x + ra[k4 * 4 + 1] * q4.y +
                   ra[k4 * 4 + 2] * q4.z + ra[k4 * 4 + 3] * q4.w;
        }
        Out[((size_t)(n0 + ni) * NR + r) * NHID + h * DK + d] = acc;
    }
}

// ---------------- RTE tables ----------------
__global__ void k_rtetab(const float* __restrict__ emb, const float* __restrict__ W,
                         const float* __restrict__ bvec) {
    __shared__ float xs[NHID];
    int tmv = blockIdx.x, c = threadIdx.x;
    xs[c] = emb[tmv * NHID + c];
    __syncthreads();
    float acc = bvec[c];
#pragma unroll 8
    for (int k = 0; k < NHID; k++) acc += xs[k] * W[k * NHID + c];
    d_rtetab[tmv * NHID + c] = acc;
}

__global__ void k_rteproj(const float* __restrict__ W, float* __restrict__ Out) {
    __shared__ float xs[NHID];
    int tmv = blockIdx.x, t = blockIdx.y, c = threadIdx.x;
    xs[c] = d_rtetab[tmv * NHID + c];
    __syncthreads();
    const float* Wt = W + (size_t)t * NHID * NHID;
    float acc = 0.f;
#pragma unroll 8
    for (int k = 0; k < NHID; k++) acc += xs[k] * Wt[k * NHID + c];
    Out[((size_t)t * MAXLEN + tmv) * NHID + c] = acc;
}

__global__ void k_vrrte(const float* __restrict__ RM) {
    __shared__ float xs[NHID];
    int tmv = blockIdx.x, r = blockIdx.y, t = blockIdx.z, c = threadIdx.x;
    xs[c] = d_Vrte[((size_t)t * MAXLEN + tmv) * NHID + c];
    __syncthreads();
    int h = c >> 5, d = c & 31;
    const float* base = RM + (size_t)(r * NH + h) * DK * DK + d;
    float acc = 0.f;
#pragma unroll
    for (int k = 0; k < DK; k++) acc += xs[h * DK + k] * base[k * DK];
    d_VRrte[(((size_t)t * NR + r) * MAXLEN + tmv) * NHID + c] = acc;
}

// ---------------- fused edge pass: logits -> exp -> denom + weighted scatter --
// exp(a)/sum(exp(a)) == exp(a-max)/sum(exp(a-max)); logits are bounded so no
// overflow hazard -> the segment-max pass is removed entirely.
__global__ __launch_bounds__(256) void k_edge(const int* __restrict__ ei,
        const int* __restrict__ et, const int* __restrict__ etime,
        const int* __restrict__ nty) {
    int e = blockIdx.x * 8 + (threadIdx.x >> 5);
    if (e >= NE) return;
    int lane = threadIdx.x & 31;
    int src = ei[e], dst = ei[NE + e];
    int r = et[e], tmv = etime[e], st = nty[src];
    const float4* K4 = (const float4*)d_Kn;
    const float4* Kr4 = (const float4*)d_Krte;
    const float4* Q4 = (const float4*)d_QR;
    float4 kv = K4[(size_t)src * 32 + lane];
    float4 kr = Kr4[((size_t)st * MAXLEN + tmv) * 32 + lane];
    float4 qv = Q4[((size_t)dst * NR + r) * 32 + lane];
    float p = (kv.x + kr.x) * qv.x + (kv.y + kr.y) * qv.y +
              (kv.z + kr.z) * qv.z + (kv.w + kr.w) * qv.w;
    p += __shfl_down_sync(0xffffffffu, p, 4);
    p += __shfl_down_sync(0xffffffffu, p, 2);
    p += __shfl_down_sync(0xffffffffu, p, 1);
    float w = expf(p);  // valid on lanes 0,8,16,24
    float w0 = __shfl_sync(0xffffffffu, w, 0);
    float w1 = __shfl_sync(0xffffffffu, w, 8);
    float w2 = __shfl_sync(0xffffffffu, w, 16);
    float w3 = __shfl_sync(0xffffffffu, w, 24);
    if (lane == 0) {
        asm volatile("red.global.add.v4.f32 [%0], {%1,%2,%3,%4};" ::
                     "l"(d_denom + (size_t)dst * NH),
                     "f"(w0), "f"(w1), "f"(w2), "f"(w3) : "memory");
    }
    int h = lane >> 3;
    float wh = (h == 0) ? w0 : ((h == 1) ? w1 : ((h == 2) ? w2 : w3));
    const float4* V4 = (const float4*)d_VR;
    const float4* Vr4 = (const float4*)d_VRrte;
    float4 vv = V4[((size_t)src * NR + r) * 32 + lane];
    float4 vr = Vr4[(((size_t)st * NR + r) * MAXLEN + tmv) * 32 + lane];
    float4 ov;
    ov.x = wh * (vv.x + vr.x); ov.y = wh * (vv.y + vr.y);
    ov.z = wh * (vv.z + vr.z); ov.w = wh * (vv.w + vr.w);
    asm volatile("red.global.add.v4.f32 [%0], {%1,%2,%3,%4};" ::
                 "l"(d_aggr + (size_t)dst * NHID + lane * 4),
                 "f"(ov.x), "f"(ov.y), "f"(ov.z), "f"(ov.w) : "memory");
}

// ---------------- normalize + GELU ----------------
__global__ void k_norm() {
    int n = blockIdx.x, c = threadIdx.x;
    float dn = d_denom[(size_t)n * NH + (c >> 5)] + 1e-16f;
    float x = d_aggr[(size_t)n * NHID + c] / dn;
    d_gbuf[(size_t)n * NHID + c] = gelu_f(x);
}

// ---------------- launch ----------------
extern "C" void kernel_launch(void* const* d_in, const int* in_sizes, int n_in,
                              void* d_out, int out_size) {
    (void)in_sizes; (void)n_in; (void)out_size;
    const float* node_feature = (const float*)d_in[0];
    const float* adapt_W = (const float*)d_in[1];
    const float* adapt_b = (const float*)d_in[2];
    const float* Wk = (const float*)d_in[3];
    const float* bk = (const float*)d_in[4];
    const float* Wq = (const float*)d_in[5];
    const float* bq = (const float*)d_in[6];
    const float* Wv = (const float*)d_in[7];
    const float* bv = (const float*)d_in[8];
    const float* Wa = (const float*)d_in[9];
    const float* ba = (const float*)d_in[10];
    const float* rel_pri = (const float*)d_in[11];
    const float* rel_att = (const float*)d_in[12];
    const float* rel_msg = (const float*)d_in[13];
    const float* skip = (const float*)d_in[14];
    const float* rte_emb = (const float*)d_in[15];
    const float* rte_W = (const float*)d_in[16];
    const float* rte_b = (const float*)d_in[17];
    const int* node_type = (const int*)d_in[18];
    const int* edge_index = (const int*)d_in[19];
    const int* edge_type = (const int*)d_in[20];
    const int* edge_time = (const int*)d_in[21];
    float* out = (float*)d_out;

    void* p;
    float *p_h, *p_h2, *p_Kn, *p_Vn, *p_Qn, *p_QR, *p_VR, *p_denom, *p_aggr,
          *p_gbuf, *p_Krte, *p_Vrte;
    int* p_cnt;
    cudaGetSymbolAddress(&p, d_h);     p_h = (float*)p;
    cudaGetSymbolAddress(&p, d_h2);    p_h2 = (float*)p;
    cudaGetSymbolAddress(&p, d_Kn);    p_Kn = (float*)p;
    cudaGetSymbolAddress(&p, d_Vn);    p_Vn = (float*)p;
    cudaGetSymbolAddress(&p, d_Qn);    p_Qn = (float*)p;
    cudaGetSymbolAddress(&p, d_QR);    p_QR = (float*)p;
    cudaGetSymbolAddress(&p, d_VR);    p_VR = (float*)p;
    cudaGetSymbolAddress(&p, d_denom); p_denom = (float*)p;
    cudaGetSymbolAddress(&p, d_aggr);  p_aggr = (float*)p;
    cudaGetSymbolAddress(&p, d_gbuf);  p_gbuf = (float*)p;
    cudaGetSymbolAddress(&p, d_Krte);  p_Krte = (float*)p;
    cudaGetSymbolAddress(&p, d_Vrte);  p_Vrte = (float*)p;
    cudaGetSymbolAddress(&p, d_cnt);   p_cnt = (int*)p;

    const int NBN = (NN + 255) / 256;
    const int GT = NN / 128 + NT + 2;  // upper bound on typed-gemm tiles
    const float inv_sqrt_dk = 0.17677669529663687f; // 1/sqrt(32)

    // type bucketing
    cudaMemsetAsync(p_cnt, 0, NT * sizeof(int));
    k_count<<<NBN, 256>>>(node_type);
    k_scan<<<1, 1>>>();
    k_scatter<<<NBN, 256>>>(node_type);

    // input adaptation: h = gelu(x @ adapt_W[t] + adapt_b[t])
    typed_gemm<INDIM, 1><<<GT, 256>>>(node_feature, adapt_W, adapt_b,
                                      nullptr, nullptr, p_h);

    const float* hin = p_h;
    for (int l = 0; l < NLAYERS; l++) {
        const float* Wk_l = Wk + (size_t)l * NT * NHID * NHID;
        const float* Wq_l = Wq + (size_t)l * NT * NHID * NHID;
        const float* Wv_l = Wv + (size_t)l * NT * NHID * NHID;
        const float* Wa_l = Wa + (size_t)l * NT * NHID * NHID;
        const float* bk_l = bk + (size_t)l * NT * NHID;
        const float* bq_l = bq + (size_t)l * NT * NHID;
        const float* bv_l = bv + (size_t)l * NT * NHID;
        const float* ba_l = ba + (size_t)l * NT * NHID;
        const float* ra_l = rel_att + (size_t)l * NR * NH * DK * DK;
        const float* rm_l = rel_msg + (size_t)l * NR * NH * DK * DK;
        const float* pri_l = rel_pri + (size_t)l * NR * NH;
        const float* skip_l = skip + (size_t)l * NT;
        float* hout = (l == NLAYERS - 1) ? out : p_h2;

        // per-node K/Q/V
        typed_gemm<NHID, 0><<<GT, 256>>>(hin, Wk_l, bk_l, nullptr, nullptr, p_Kn);
        typed_gemm<NHID, 0><<<GT, 256>>>(hin, Wq_l, bq_l, nullptr, nullptr, p_Qn);
        typed_gemm<NHID, 0><<<GT, 256>>>(hin, Wv_l, bv_l, nullptr, nullptr, p_Vn);

        // RTE tables
        k_rtetab<<<MAXLEN, NHID>>>(rte_emb, rte_W + (size_t)l * NHID * NHID,
                                   rte_b + (size_t)l * NHID);
        {
            dim3 g(MAXLEN, NT);
            k_rteproj<<<g, NHID>>>(Wk_l, p_Krte);
            k_rteproj<<<g, NHID>>>(Wv_l, p_Vrte);
        }
        {
            dim3 g(MAXLEN, NR, NT);
            k_vrrte<<<g, NHID>>>(rm_l);
        }

        // relation-transformed Q and V per node
        {
            int gb = (NN + 63) / 64;
            qrvr_kernel<true><<<gb, 640>>>(p_Qn, ra_l, pri_l, inv_sqrt_dk, p_QR);
            qrvr_kernel<false><<<gb, 640>>>(p_Vn, rm_l, nullptr, 1.0f, p_VR);
        }

        // fused edge pass
        cudaMemsetAsync(p_denom, 0, (size_t)NN * NH * sizeof(float));
        cudaMemsetAsync(p_aggr, 0, (size_t)NN * NHID * sizeof(float));
        k_edge<<<NE / 8, 256>>>(edge_index, edge_type, edge_time, node_type);
        k_norm<<<NN, NHID>>>();

        // output transform + gated skip
        typed_gemm<NHID, 2><<<GT, 256>>>(p_gbuf, Wa_l, ba_l, skip_l, hin, hout);
        hin = hout;
        if (l == 0) { float* tmp = p_h; p_h = p_h2; p_h2 = tmp; }
    }
}

// round 7
// speedup vs baseline: 1.1865x; 1.1865x over previous
#include <cuda_runtime.h>
#include <math.h>

#define NN 50000
#define NE 400000
#define NHID 128
#define INDIM 256
#define NT 4
#define NR 5
#define NH 4
#define DK 32
#define MAXLEN 240
#define NLAYERS 2

// ---------------- scratch (device globals; no allocation) ----------------
__device__ float d_h[(size_t)NN * NHID];
__device__ float d_h2[(size_t)NN * NHID];
__device__ float d_Kn[(size_t)NN * NHID];
__device__ float d_Vn[(size_t)NN * NHID];
__device__ float d_Qn[(size_t)NN * NHID];
__device__ float d_QR[(size_t)NN * NR * NHID];
__device__ float d_VR[(size_t)NN * NR * NHID];
__device__ float d_denom[(size_t)NN * NH];
__device__ float d_aggr[(size_t)NN * NHID];
__device__ float d_rtetab[MAXLEN * NHID];
__device__ float d_Krte[NT * MAXLEN * NHID];
__device__ float d_Vrte[NT * MAXLEN * NHID];
__device__ float d_VRrte[(size_t)NT * NR * MAXLEN * NHID];
__device__ int d_perm[NN];
__device__ int d_cnt[NT];
__device__ int d_off[NT + 1];
__device__ int d_cur[NT];

__device__ __forceinline__ float gelu_f(float x) {
    return 0.5f * x * (1.0f + erff(x * 0.70710678118654752440f));
}

// ---------------- type bucketing (counting sort by node type) ----------------
__global__ void k_count(const int* __restrict__ nt) {
    int n = blockIdx.x * 256 + threadIdx.x;
    if (n < NN) atomicAdd(&d_cnt[nt[n]], 1);
}
__global__ void k_scan() {
    int s = 0;
    for (int t = 0; t < NT; t++) { d_off[t] = s; d_cur[t] = s; s += d_cnt[t]; }
    d_off[NT] = s;
}
__global__ void k_scatter(const int* __restrict__ nt) {
    int n = blockIdx.x * 256 + threadIdx.x;
    if (n < NN) {
        int p = atomicAdd(&d_cur[nt[n]], 1);
        d_perm[p] = n;
    }
}

// ---------------- type-selected GEMM: C[n,:] = A[n,:] @ W[type[n]] + b ----------------
// 64x128 tile, 256 threads, 8x4 per thread, BK=32 (round-2 geometry: 74 regs).
// EPI: 0 = bias, 1 = bias+GELU, 2 = bias then v*sig(skip[t]) + Hres*(1-sig)
// NORMA: A rows are d_aggr; apply x -> gelu(x / denom[row,head]) while loading.
//        (BK == 32 == head width, so head index is k0>>5, constant per k-step.)
template <int K, int EPI, int NORMA>
__global__ __launch_bounds__(256) void typed_gemm(
    const float* __restrict__ A, const float* __restrict__ W,
    const float* __restrict__ Bias, const float* __restrict__ skipv,
    const float* __restrict__ Hres, float* __restrict__ C)
{
    int b = blockIdx.x;
    int t = -1, row0 = 0, mrows = 0;
#pragma unroll
    for (int tt = 0; tt < NT; tt++) {
        if (t < 0) {
            int c = d_cnt[tt];
            int ntile = (c + 63) >> 6;
            if (b < ntile) {
                t = tt;
                row0 = d_off[tt] + b * 64;
                mrows = c - b * 64;
                if (mrows > 64) mrows = 64;
            } else {
                b -= ntile;
            }
        }
    }
    if (t < 0) return;

    __shared__ float As[32][68];
    __shared__ float Bs[32][128];
    __shared__ int rowidx[64];
    __shared__ float rdn[64][4];
    int tid = threadIdx.x;
    if (tid < 64) {
        int m = tid < mrows ? tid : (mrows - 1);
        int gr = d_perm[row0 + m];
        rowidx[tid] = gr;
        if (NORMA) {
            float4 dn = *(const float4*)(d_denom + (size_t)gr * NH);
            rdn[tid][0] = 1.f / (dn.x + 1e-16f);
            rdn[tid][1] = 1.f / (dn.y + 1e-16f);
            rdn[tid][2] = 1.f / (dn.z + 1e-16f);
            rdn[tid][3] = 1.f / (dn.w + 1e-16f);
        }
    }
    __syncthreads();

    const float* Wt = W + (size_t)t * K * NHID;
    float acc[8][4];
#pragma unroll
    for (int j = 0; j < 8; j++)
#pragma unroll
        for (int i = 0; i < 4; i++) acc[j][i] = 0.f;
    int tm = tid >> 5, tn = tid & 31;

    for (int k0 = 0; k0 < K; k0 += 32) {
#pragma unroll
        for (int it = 0; it < 2; it++) {
            int s = tid + it * 256;
            int m = s >> 3, k4 = (s & 7) * 4;
            float4 av = *(const float4*)(A + (size_t)rowidx[m] * K + k0 + k4);
            if (NORMA) {
                float dn = rdn[m][k0 >> 5];
                av.x = gelu_f(av.x * dn); av.y = gelu_f(av.y * dn);
                av.z = gelu_f(av.z * dn); av.w = gelu_f(av.w * dn);
            }
            As[k4 + 0][m] = av.x; As[k4 + 1][m] = av.y;
            As[k4 + 2][m] = av.z; As[k4 + 3][m] = av.w;
        }
#pragma unroll
        for (int it = 0; it < 4; it++) {
            int s = tid + it * 256;
            int kk = s >> 5, c4 = (s & 31) * 4;
            *(float4*)&Bs[kk][c4] = *(const float4*)(Wt + (size_t)(k0 + kk) * NHID + c4);
        }
        __syncthreads();
#pragma unroll
        for (int kk = 0; kk < 32; kk++) {
            float4 a0 = *(const float4*)&As[kk][tm * 8];
            float4 a1 = *(const float4*)&As[kk][tm * 8 + 4];
            float4 bv = *(const float4*)&Bs[kk][tn * 4];
            float av[8] = {a0.x, a0.y, a0.z, a0.w, a1.x, a1.y, a1.z, a1.w};
#pragma unroll
            for (int j = 0; j < 8; j++) {
                acc[j][0] += av[j] * bv.x;
                acc[j][1] += av[j] * bv.y;
                acc[j][2] += av[j] * bv.z;
                acc[j][3] += av[j] * bv.w;
            }
        }
        __syncthreads();
    }

    float4 bias = *(const float4*)(Bias + t * NHID + tn * 4);
    float sg = 0.f, om = 0.f;
    if (EPI == 2) {
        float sv = skipv[t];
        sg = 1.f / (1.f + expf(-sv));
        om = 1.f - sg;
    }
#pragma unroll
    for (int j = 0; j < 8; j++) {
        int m = tm * 8 + j;
        if (m < mrows) {
            int gr = rowidx[m];
            float4 v;
            v.x = acc[j][0] + bias.x; v.y = acc[j][1] + bias.y;
            v.z = acc[j][2] + bias.z; v.w = acc[j][3] + bias.w;
            if (EPI == 1) {
                v.x = gelu_f(v.x); v.y = gelu_f(v.y);
                v.z = gelu_f(v.z); v.w = gelu_f(v.w);
            }
            if (EPI == 2) {
                float4 hv = *(const float4*)(Hres + (size_t)gr * NHID + tn * 4);
                v.x = v.x * sg + hv.x * om; v.y = v.y * sg + hv.y * om;
                v.z = v.z * sg + hv.z * om; v.w = v.w * sg + hv.w * om;
            }
            *(float4*)(C + (size_t)gr * NHID + tn * 4) = v;
        }
    }
}

// ---------------- block-diagonal relation transform ----------------
// TRANS (QR): Out[n,r,h*32+d] = s * sum_k M[r,h,d,k] * In[n,h*32+k]
// !TRANS (VR): Out[n,r,h*32+d] =     sum_k In[n,h*32+k] * M[r,h,k,d]
template <bool TRANS>
__global__ __launch_bounds__(640) void qrvr_kernel(
    const float* __restrict__ In, const float* __restrict__ M,
    const float* __restrict__ pri, float scale, float* __restrict__ Out)
{
    int tid = threadIdx.x;
    int r = tid >> 7, rem = tid & 127, h = rem >> 5, d = rem & 31;
    float s = scale;
    if (pri) s *= pri[r * NH + h];
    float ra[DK];
    if (TRANS) {
        const float* base = M + (((size_t)(r * NH + h) * DK + d) * DK);
#pragma unroll
        for (int k = 0; k < DK; k++) ra[k] = base[k] * s;
    } else {
        const float* base = M + ((size_t)(r * NH + h) * DK * DK + d);
#pragma unroll
        for (int k = 0; k < DK; k++) ra[k] = base[k * DK] * s;
    }
    __shared__ float qs[64][NHID];
    int n0 = blockIdx.x * 64;
    for (int i = tid; i < 64 * NHID; i += 640) {
        int ni = i >> 7, c = i & 127;
        int n = n0 + ni;
        qs[ni][c] = (n < NN) ? In[(size_t)n * NHID + c] : 0.f;
    }
    __syncthreads();
    int nmax = NN - n0;
    if (nmax > 64) nmax = 64;
    for (int ni = 0; ni < nmax; ni++) {
        float acc = 0.f;
#pragma unroll
        for (int k4 = 0; k4 < 8; k4++) {
            float4 q4 = *(const float4*)&qs[ni][h * DK + k4 * 4];
            acc += ra[k4 * 4] * q4.x + ra[k4 * 4 + 1] * q4.y +
                   ra[k4 * 4 + 2] * q4.z + ra[k4 * 4 + 3] * q4.w;
        }
        Out[((size_t)(n0 + ni) * NR + r) * NHID + h * DK + d] = acc;
    }
}

// ---------------- RTE tables ----------------
__global__ void k_rtetab(const float* __restrict__ emb, const float* __restrict__ W,
                         const float* __restrict__ bvec) {
    __shared__ float xs[NHID];
    int tmv = blockIdx.x, c = threadIdx.x;
    xs[c] = emb[tmv * NHID + c];
    __syncthreads();
    float acc = bvec[c];
#pragma unroll 8
    for (int k = 0; k < NHID; k++) acc += xs[k] * W[k * NHID + c];
    d_rtetab[tmv * NHID + c] = acc;
}

__global__ void k_rteproj(const float* __restrict__ W, float* __restrict__ Out) {
    __shared__ float xs[NHID];
    int tmv = blockIdx.x, t = blockIdx.y, c = threadIdx.x;
    xs[c] = d_rtetab[tmv * NHID + c];
    __syncthreads();
    const float* Wt = W + (size_t)t * NHID * NHID;
    float acc = 0.f;
#pragma unroll 8
    for (int k = 0; k < NHID; k++) acc += xs[k] * Wt[k * NHID + c];
    Out[((size_t)t * MAXLEN + tmv) * NHID + c] = acc;
}

__global__ void k_vrrte(const float* __restrict__ RM) {
    __shared__ float xs[NHID];
    int tmv = blockIdx.x, r = blockIdx.y, t = blockIdx.z, c = threadIdx.x;
    xs[c] = d_Vrte[((size_t)t * MAXLEN + tmv) * NHID + c];
    __syncthreads();
    int h = c >> 5, d = c & 31;
    const float* base = RM + (size_t)(r * NH + h) * DK * DK + d;
    float acc = 0.f;
#pragma unroll
    for (int k = 0; k < DK; k++) acc += xs[h * DK + k] * base[k * DK];
    d_VRrte[(((size_t)t * NR + r) * MAXLEN + tmv) * NHID + c] = acc;
}

// ---------------- fused edge pass: logits -> exp -> denom + weighted scatter --
// exp(a)/sum(exp(a)) == exp(a-max)/sum(exp(a-max)); logits bounded -> no max pass.
__global__ __launch_bounds__(256) void k_edge(const int* __restrict__ ei,
        const int* __restrict__ et, const int* __restrict__ etime,
        const int* __restrict__ nty) {
    int e = blockIdx.x * 8 + (threadIdx.x >> 5);
    if (e >= NE) return;
    int lane = threadIdx.x & 31;
    int src = ei[e], dst = ei[NE + e];
    int r = et[e], tmv = etime[e], st = nty[src];
    const float4* K4 = (const float4*)d_Kn;
    const float4* Kr4 = (const float4*)d_Krte;
    const float4* Q4 = (const float4*)d_QR;
    float4 kv = K4[(size_t)src * 32 + lane];
    float4 kr = Kr4[((size_t)st * MAXLEN + tmv) * 32 + lane];
    float4 qv = Q4[((size_t)dst * NR + r) * 32 + lane];
    float p = (kv.x + kr.x) * qv.x + (kv.y + kr.y) * qv.y +
              (kv.z + kr.z) * qv.z + (kv.w + kr.w) * qv.w;
    p += __shfl_down_sync(0xffffffffu, p, 4);
    p += __shfl_down_sync(0xffffffffu, p, 2);
    p += __shfl_down_sync(0xffffffffu, p, 1);
    float w = expf(p);  // valid on lanes 0,8,16,24
    float w0 = __shfl_sync(0xffffffffu, w, 0);
    float w1 = __shfl_sync(0xffffffffu, w, 8);
    float w2 = __shfl_sync(0xffffffffu, w, 16);
    float w3 = __shfl_sync(0xffffffffu, w, 24);
    if (lane == 0) {
        asm volatile("red.global.add.v4.f32 [%0], {%1,%2,%3,%4};" ::
                     "l"(d_denom + (size_t)dst * NH),
                     "f"(w0), "f"(w1), "f"(w2), "f"(w3) : "memory");
    }
    int h = lane >> 3;
    float wh = (h == 0) ? w0 : ((h == 1) ? w1 : ((h == 2) ? w2 : w3));
    const float4* V4 = (const float4*)d_VR;
    const float4* Vr4 = (const float4*)d_VRrte;
    float4 vv = V4[((size_t)src * NR + r) * 32 + lane];
    float4 vr = Vr4[(((size_t)st * NR + r) * MAXLEN + tmv) * 32 + lane];
    float4 ov;
    ov.x = wh * (vv.x + vr.x); ov.y = wh * (vv.y + vr.y);
    ov.z = wh * (vv.z + vr.z); ov.w = wh * (vv.w + vr.w);
    asm volatile("red.global.add.v4.f32 [%0], {%1,%2,%3,%4};" ::
                 "l"(d_aggr + (size_t)dst * NHID + lane * 4),
                 "f"(ov.x), "f"(ov.y), "f"(ov.z), "f"(ov.w) : "memory");
}

// ---------------- launch ----------------
extern "C" void kernel_launch(void* const* d_in, const int* in_sizes, int n_in,
                              void* d_out, int out_size) {
    (void)in_sizes; (void)n_in; (void)out_size;
    const float* node_feature = (const float*)d_in[0];
    const float* adapt_W = (const float*)d_in[1];
    const float* adapt_b = (const float*)d_in[2];
    const float* Wk = (const float*)d_in[3];
    const float* bk = (const float*)d_in[4];
    const float* Wq = (const float*)d_in[5];
    const float* bq = (const float*)d_in[6];
    const float* Wv = (const float*)d_in[7];
    const float* bv = (const float*)d_in[8];
    const float* Wa = (const float*)d_in[9];
    const float* ba = (const float*)d_in[10];
    const float* rel_pri = (const float*)d_in[11];
    const float* rel_att = (const float*)d_in[12];
    const float* rel_msg = (const float*)d_in[13];
    const float* skip = (const float*)d_in[14];
    const float* rte_emb = (const float*)d_in[15];
    const float* rte_W = (const float*)d_in[16];
    const float* rte_b = (const float*)d_in[17];
    const int* node_type = (const int*)d_in[18];
    const int* edge_index = (const int*)d_in[19];
    const int* edge_type = (const int*)d_in[20];
    const int* edge_time = (const int*)d_in[21];
    float* out = (float*)d_out;

    void* p;
    float *p_h, *p_h2, *p_Kn, *p_Vn, *p_Qn, *p_QR, *p_VR, *p_denom, *p_aggr,
          *p_Krte, *p_Vrte;
    int* p_cnt;
    cudaGetSymbolAddress(&p, d_h);     p_h = (float*)p;
    cudaGetSymbolAddress(&p, d_h2);    p_h2 = (float*)p;
    cudaGetSymbolAddress(&p, d_Kn);    p_Kn = (float*)p;
    cudaGetSymbolAddress(&p, d_Vn);    p_Vn = (float*)p;
    cudaGetSymbolAddress(&p, d_Qn);    p_Qn = (float*)p;
    cudaGetSymbolAddress(&p, d_QR);    p_QR = (float*)p;
    cudaGetSymbolAddress(&p, d_VR);    p_VR = (float*)p;
    cudaGetSymbolAddress(&p, d_denom); p_denom = (float*)p;
    cudaGetSymbolAddress(&p, d_aggr);  p_aggr = (float*)p;
    cudaGetSymbolAddress(&p, d_Krte);  p_Krte = (float*)p;
    cudaGetSymbolAddress(&p, d_Vrte);  p_Vrte = (float*)p;
    cudaGetSymbolAddress(&p, d_cnt);   p_cnt = (int*)p;

    const int NBN = (NN + 255) / 256;
    const int GT = NN / 64 + NT + 2;   // upper bound on typed-gemm tiles
    const float inv_sqrt_dk = 0.17677669529663687f; // 1/sqrt(32)

    // type bucketing
    cudaMemsetAsync(p_cnt, 0, NT * sizeof(int));
    k_count<<<NBN, 256>>>(node_type);
    k_scan<<<1, 1>>>();
    k_scatter<<<NBN, 256>>>(node_type);

    // input adaptation: h = gelu(x @ adapt_W[t] + adapt_b[t])
    typed_gemm<INDIM, 1, 0><<<GT, 256>>>(node_feature, adapt_W, adapt_b,
                                         nullptr, nullptr, p_h);

    const float* hin = p_h;
    for (int l = 0; l < NLAYERS; l++) {
        const float* Wk_l = Wk + (size_t)l * NT * NHID * NHID;
        const float* Wq_l = Wq + (size_t)l * NT * NHID * NHID;
        const float* Wv_l = Wv + (size_t)l * NT * NHID * NHID;
        const float* Wa_l = Wa + (size_t)l * NT * NHID * NHID;
        const float* bk_l = bk + (size_t)l * NT * NHID;
        const float* bq_l = bq + (size_t)l * NT * NHID;
        const float* bv_l = bv + (size_t)l * NT * NHID;
        const float* ba_l = ba + (size_t)l * NT * NHID;
        const float* ra_l = rel_att + (size_t)l * NR * NH * DK * DK;
        const float* rm_l = rel_msg + (size_t)l * NR * NH * DK * DK;
        const float* pri_l = rel_pri + (size_t)l * NR * NH;
        const float* skip_l = skip + (size_t)l * NT;
        float* hout = (l == NLAYERS - 1) ? out : p_h2;

        // per-node K/Q/V
        typed_gemm<NHID, 0, 0><<<GT, 256>>>(hin, Wk_l, bk_l, nullptr, nullptr, p_Kn);
        typed_gemm<NHID, 0, 0><<<GT, 256>>>(hin, Wq_l, bq_l, nullptr, nullptr, p_Qn);
        typed_gemm<NHID, 0, 0><<<GT, 256>>>(hin, Wv_l, bv_l, nullptr, nullptr, p_Vn);

        // RTE tables
        k_rtetab<<<MAXLEN, NHID>>>(rte_emb, rte_W + (size_t)l * NHID * NHID,
                                   rte_b + (size_t)l * NHID);
        {
            dim3 g(MAXLEN, NT);
            k_rteproj<<<g, NHID>>>(Wk_l, p_Krte);
            k_rteproj<<<g, NHID>>>(Wv_l, p_Vrte);
        }
        {
            dim3 g(MAXLEN, NR, NT);
            k_vrrte<<<g, NHID>>>(rm_l);
        }

        // relation-transformed Q and V per node
        {
            int gb = (NN + 63) / 64;
            qrvr_kernel<true><<<gb, 640>>>(p_Qn, ra_l, pri_l, inv_sqrt_dk, p_QR);
            qrvr_kernel<false><<<gb, 640>>>(p_Vn, rm_l, nullptr, 1.0f, p_VR);
        }

        // fused edge pass
        cudaMemsetAsync(p_denom, 0, (size_t)NN * NH * sizeof(float));
        cudaMemsetAsync(p_aggr, 0, (size_t)NN * NHID * sizeof(float));
        k_edge<<<NE / 8, 256>>>(edge_index, edge_type, edge_time, node_type);

        // output transform + gated skip, with normalize+GELU fused into A-load
        typed_gemm<NHID, 2, 1><<<GT, 256>>>(p_aggr, Wa_l, ba_l, skip_l, hin, hout);
        hin = hout;
        if (l == 0) { float* tmp = p_h; p_h = p_h2; p_h2 = tmp; }
    }
}